// round 1
// baseline (speedup 1.0000x reference)
#include <cuda_runtime.h>

// ---------------------------------------------------------------------------
// Net_multi_11390253269716: 3-level GCN U-Net on a 784x480 grid, C=32.
// Inputs (metadata order):
//  0 x[N0,4] 1 fc1_w[4,32] 2 fc1_b[32] 3 w1 4 b1 5 w2 6 b2 7 w3 8 b3
//  9 w4 10 b4 11 w5 12 b5 13 fc2_w[32,3] 14 fc2_b[3]
//  15 idx0 16 idx1 17 idx2 (arange -> identity) 18 ei0[2,4N0] 19 ei1 20 ei2
// Output: [N0,3] float32
// ---------------------------------------------------------------------------

#define NXg 784
#define NYg 480
#define C 32
#define N0 (NXg * NYg)        // 376320
#define N1 (N0 / 4)           // 94080
#define N2 (N0 / 16)          // 23520
#define E0 (4 * N0)
#define E1 (4 * N1)
#define E2 (4 * N2)

// Scratch (static __device__ arrays; no allocation in kernel_launch).
__device__ float g_A0[N0 * C];   // fc1 output (relu'd); reused as U0 later
__device__ float g_Y [N0 * C];   // x@w temp for every GCN
__device__ float g_H [N0 * C];   // GCN1 output (pre-relu), needed for residual
__device__ float g_G5[N0 * C];   // GCN5 output (pre-relu)
__device__ float g_D1[N1 * C];
__device__ float g_G2[N1 * C];
__device__ float g_U1[N1 * C];
__device__ float g_G4[N1 * C];
__device__ float g_D2[N2 * C];
__device__ float g_G3[N2 * C];
__device__ float g_dinv0[N0];
__device__ float g_dinv1[N1];
__device__ float g_dinv2[N2];

// ---------------- degree / norm ----------------
__global__ void deg_init(float* d, int n) {
    int i = blockIdx.x * blockDim.x + threadIdx.x;
    if (i < n) d[i] = 1.0f;               // self loop
}
__global__ void deg_acc(const int* __restrict__ dst, float* d, int ne) {
    int e = blockIdx.x * blockDim.x + threadIdx.x;
    if (e < ne) atomicAdd(&d[dst[e]], 1.0f);
}
__global__ void deg_rsqrt(float* d, int n) {
    int i = blockIdx.x * blockDim.x + threadIdx.x;
    if (i < n) d[i] = rsqrtf(d[i]);
}

// ---------------- fc1: [n,4] @ [4,32] + b, relu ----------------
__global__ void fc1_kernel(const float* __restrict__ x,
                           const float* __restrict__ w,
                           const float* __restrict__ b,
                           float* __restrict__ out, int n) {
    int t = blockIdx.x * blockDim.x + threadIdx.x;
    int node = t >> 5;
    int lane = t & 31;
    if (node >= n) return;
    float acc = __ldg(&b[lane]);
    #pragma unroll
    for (int k = 0; k < 4; k++)
        acc += __ldg(&x[node * 4 + k]) * __ldg(&w[k * C + lane]);
    out[node * C + lane] = fmaxf(acc, 0.0f);
}

// ---------------- GEMM: y[n,32] = x[n,32] @ w[32,32] ----------------
__global__ void gemm32(const float* __restrict__ x,
                       const float* __restrict__ w,
                       float* __restrict__ y, int n) {
    __shared__ float sw[C][C];
    int tid = threadIdx.x;
    for (int i = tid; i < C * C; i += blockDim.x) sw[i / C][i % C] = w[i];
    __syncthreads();
    int lane = tid & 31;
    int row = blockIdx.x * (blockDim.x >> 5) + (tid >> 5);
    if (row >= n) return;
    float xv = x[row * C + lane];
    float acc = 0.0f;
    #pragma unroll
    for (int k = 0; k < C; k++)
        acc += __shfl_sync(0xffffffffu, xv, k) * sw[k][lane];
    y[row * C + lane] = acc;
}

// ---------------- out = y * dinv^2 + b (self loop + bias) ----------------
__global__ void self_bias(const float* __restrict__ y,
                          const float* __restrict__ dinv,
                          const float* __restrict__ b,
                          float* __restrict__ out, int n) {
    int i = blockIdx.x * blockDim.x + threadIdx.x;
    if (i >= n * C) return;
    int node = i >> 5;      // C == 32
    int c = i & 31;
    float di = dinv[node];
    out[i] = y[i] * di * di + __ldg(&b[c]);
}

// ---------------- edge scatter: warp per edge ----------------
__global__ void scatter_edges(const float* __restrict__ y,
                              const float* __restrict__ dinv,
                              const int* __restrict__ src,
                              const int* __restrict__ dst,
                              float* __restrict__ out, int ne) {
    int t = blockIdx.x * blockDim.x + threadIdx.x;
    int e = t >> 5;
    int lane = t & 31;
    if (e >= ne) return;
    int s = __ldg(&src[e]);
    int d = __ldg(&dst[e]);
    float norm = dinv[s] * dinv[d];
    atomicAdd(&out[d * C + lane], y[s * C + lane] * norm);
}

// ---------------- downsample (::2,::2) with relu ----------------
__global__ void down_relu(const float* __restrict__ in, float* __restrict__ out,
                          int hx, int hy, int win) {
    int i = blockIdx.x * blockDim.x + threadIdx.x;
    int total = hx * hy * C;
    if (i >= total) return;
    int node = i >> 5;
    int c = i & 31;
    int ix = node / hy;
    int iy = node % hy;
    int sn = (2 * ix) * win + 2 * iy;
    out[i] = fmaxf(in[sn * C + c], 0.0f);
}

// ---------------- out = relu(base) + relu(up2(coarse)) ----------------
__global__ void up_add(const float* __restrict__ base,
                       const float* __restrict__ coarse,
                       float* __restrict__ out, int hx, int hy) {
    int i = blockIdx.x * blockDim.x + threadIdx.x;
    int total = hx * hy * C;
    if (i >= total) return;
    int node = i >> 5;
    int c = i & 31;
    int ix = node / hy;
    int iy = node % hy;
    int cn = (ix >> 1) * (hy >> 1) + (iy >> 1);
    out[i] = fmaxf(base[node * C + c], 0.0f) + fmaxf(coarse[cn * C + c], 0.0f);
}

// ---------------- fc2: relu(h)[n,32] @ [32,3] + b ----------------
__global__ void fc2_kernel(const float* __restrict__ h,
                           const float* __restrict__ w,
                           const float* __restrict__ b,
                           float* __restrict__ out, int n) {
    int t = blockIdx.x * blockDim.x + threadIdx.x;
    int node = t >> 5;
    int lane = t & 31;
    if (node >= n) return;
    float v = fmaxf(h[node * C + lane], 0.0f);
    #pragma unroll
    for (int j = 0; j < 3; j++) {
        float p = v * __ldg(&w[lane * 3 + j]);
        #pragma unroll
        for (int off = 16; off; off >>= 1)
            p += __shfl_down_sync(0xffffffffu, p, off);
        if (lane == 0) out[node * 3 + j] = p + __ldg(&b[j]);
    }
}

// ---------------------------------------------------------------------------
static inline int ceil_div(int a, int b) { return (a + b - 1) / b; }

static void run_gcn(const float* xin, const float* w, const float* b,
                    const int* ei, const float* dinv,
                    float* ybuf, float* outbuf, int n, int ne) {
    const int TB = 256;
    gemm32<<<ceil_div(n, TB / 32), TB>>>(xin, w, ybuf, n);
    self_bias<<<ceil_div(n * C, TB), TB>>>(ybuf, dinv, b, outbuf, n);
    scatter_edges<<<ceil_div(ne * 32, TB), TB>>>(ybuf, dinv, ei, ei + ne, outbuf, ne);
}

extern "C" void kernel_launch(void* const* d_in, const int* in_sizes, int n_in,
                              void* d_out, int out_size) {
    const float* x     = (const float*)d_in[0];
    const float* fc1_w = (const float*)d_in[1];
    const float* fc1_b = (const float*)d_in[2];
    const float* w1 = (const float*)d_in[3];  const float* b1 = (const float*)d_in[4];
    const float* w2 = (const float*)d_in[5];  const float* b2 = (const float*)d_in[6];
    const float* w3 = (const float*)d_in[7];  const float* b3 = (const float*)d_in[8];
    const float* w4 = (const float*)d_in[9];  const float* b4 = (const float*)d_in[10];
    const float* w5 = (const float*)d_in[11]; const float* b5 = (const float*)d_in[12];
    const float* fc2_w = (const float*)d_in[13];
    const float* fc2_b = (const float*)d_in[14];
    const int* ei0 = (const int*)d_in[18];
    const int* ei1 = (const int*)d_in[19];
    const int* ei2 = (const int*)d_in[20];
    float* out = (float*)d_out;

    float *A0, *Y, *H, *G5, *D1, *G2, *U1, *G4, *D2, *G3, *dv0, *dv1, *dv2;
    cudaGetSymbolAddress((void**)&A0, g_A0);
    cudaGetSymbolAddress((void**)&Y,  g_Y);
    cudaGetSymbolAddress((void**)&H,  g_H);
    cudaGetSymbolAddress((void**)&G5, g_G5);
    cudaGetSymbolAddress((void**)&D1, g_D1);
    cudaGetSymbolAddress((void**)&G2, g_G2);
    cudaGetSymbolAddress((void**)&U1, g_U1);
    cudaGetSymbolAddress((void**)&G4, g_G4);
    cudaGetSymbolAddress((void**)&D2, g_D2);
    cudaGetSymbolAddress((void**)&G3, g_G3);
    cudaGetSymbolAddress((void**)&dv0, g_dinv0);
    cudaGetSymbolAddress((void**)&dv1, g_dinv1);
    cudaGetSymbolAddress((void**)&dv2, g_dinv2);

    const int TB = 256;

    // Degrees -> dinv for each level (deg over dst, incl. self loop).
    deg_init<<<ceil_div(N0, TB), TB>>>(dv0, N0);
    deg_acc<<<ceil_div(E0, TB), TB>>>(ei0 + E0, dv0, E0);
    deg_rsqrt<<<ceil_div(N0, TB), TB>>>(dv0, N0);

    deg_init<<<ceil_div(N1, TB), TB>>>(dv1, N1);
    deg_acc<<<ceil_div(E1, TB), TB>>>(ei1 + E1, dv1, E1);
    deg_rsqrt<<<ceil_div(N1, TB), TB>>>(dv1, N1);

    deg_init<<<ceil_div(N2, TB), TB>>>(dv2, N2);
    deg_acc<<<ceil_div(E2, TB), TB>>>(ei2 + E2, dv2, E2);
    deg_rsqrt<<<ceil_div(N2, TB), TB>>>(dv2, N2);

    // fc1 + relu
    fc1_kernel<<<ceil_div(N0 * 32, TB), TB>>>(x, fc1_w, fc1_b, A0, N0);

    // GCN1 (level 0): H = gcn(A0); h = relu(H) applied by consumers
    run_gcn(A0, w1, b1, ei0, dv0, Y, H, N0, E0);

    // Downsample relu(H) -> D1 [392x240]
    down_relu<<<ceil_div(N1 * C, TB), TB>>>(H, D1, NXg / 2, NYg / 2, NYg);

    // GCN2 (level 1)
    run_gcn(D1, w2, b2, ei1, dv1, Y, G2, N1, E1);

    // Downsample relu(G2) -> D2 [196x120]
    down_relu<<<ceil_div(N2 * C, TB), TB>>>(G2, D2, NXg / 4, NYg / 4, NYg / 2);

    // GCN3 (level 2)
    run_gcn(D2, w3, b3, ei2, dv2, Y, G3, N2, E2);

    // U1 = relu(G2) + up2(relu(G3))
    up_add<<<ceil_div(N1 * C, TB), TB>>>(G2, G3, U1, NXg / 2, NYg / 2);

    // GCN4 (level 1)
    run_gcn(U1, w4, b4, ei1, dv1, Y, G4, N1, E1);

    // U0 = relu(H) + up2(relu(G4))   (reuse A0 as U0; A0 dead after GCN1 gemm)
    up_add<<<ceil_div(N0 * C, TB), TB>>>(H, G4, A0, NXg, NYg);

    // GCN5 (level 0)
    run_gcn(A0, w5, b5, ei0, dv0, Y, G5, N0, E0);

    // fc2: relu(G5) @ fc2_w + fc2_b -> out [N0,3]
    fc2_kernel<<<ceil_div(N0 * 32, TB), TB>>>(G5, fc2_w, fc2_b, out, N0);

    (void)in_sizes; (void)n_in; (void)out_size;
}

// round 2
// speedup vs baseline: 2.5919x; 2.5919x over previous
#include <cuda_runtime.h>

// Net_multi_11390253269716: 3-level GCN U-Net, 784x480 grid, C=32.
// R2: fused gemm+epilogue+resample, float4 everywhere, vec4 reductions.

#define NXg 784
#define NYg 480
#define C 32
#define N0 (NXg * NYg)        // 376320
#define N1 (N0 / 4)           // 94080
#define N2 (N0 / 16)          // 23520
#define E0 (4 * N0)
#define E1 (4 * N1)
#define E2 (4 * N2)

// Scratch (float4 for guaranteed 16B alignment).
__device__ float4 g_Y [N0 * 8];   // x@w temp (per-level prefix reuse)
__device__ float4 g_H [N0 * 8];   // GCN1 out (pre-relu)
__device__ float4 g_G5[N0 * 8];
__device__ float4 g_G2[N1 * 8];
__device__ float4 g_G4[N1 * 8];
__device__ float4 g_G3[N2 * 8];
__device__ float g_dv0[N0];
__device__ float g_dv1[N1];
__device__ float g_dv2[N2];

__device__ __forceinline__ float4 relu4(float4 v) {
    v.x = fmaxf(v.x, 0.f); v.y = fmaxf(v.y, 0.f);
    v.z = fmaxf(v.z, 0.f); v.w = fmaxf(v.w, 0.f);
    return v;
}

// ---------------- degree / norm (4 launches total) ----------------
__global__ void deg_init_all(float* dv0, float* dv1, float* dv2) {
    int i = blockIdx.x * blockDim.x + threadIdx.x;
    if (i < N0) dv0[i] = 1.0f;
    else if (i < N0 + N1) dv1[i - N0] = 1.0f;
    else if (i < N0 + N1 + N2) dv2[i - N0 - N1] = 1.0f;
}
__global__ void deg_acc(const int* __restrict__ dst, float* dv, int ne) {
    int e = blockIdx.x * blockDim.x + threadIdx.x;
    if (e < ne) atomicAdd(&dv[dst[e]], 1.0f);
}
__global__ void deg_acc2(const int* __restrict__ d1, float* dv1,
                         const int* __restrict__ d2, float* dv2) {
    int e = blockIdx.x * blockDim.x + threadIdx.x;
    if (e < E1) atomicAdd(&dv1[d1[e]], 1.0f);
    else if (e < E1 + E2) atomicAdd(&dv2[d2[e - E1]], 1.0f);
}
__global__ void deg_rsqrt_all(float* dv0, float* dv1, float* dv2) {
    int i = blockIdx.x * blockDim.x + threadIdx.x;
    if (i < N0) dv0[i] = rsqrtf(dv0[i]);
    else if (i < N0 + N1) dv1[i - N0] = rsqrtf(dv1[i - N0]);
    else if (i < N0 + N1 + N2) dv2[i - N0 - N1] = rsqrtf(dv2[i - N0 - N1]);
}

// ---------------- gemm core: 8 threads/node, float4 lanes ----------------
// Computes acc = x_row @ w (32x32), writes Y = acc and OUT = acc*dinv^2 + b.
__device__ __forceinline__ void gemm_core(
    float4 xq, const float4* sw, int node, int sub,
    const float* __restrict__ bias, const float* __restrict__ dinv,
    float4* __restrict__ Y, float4* __restrict__ OUT)
{
    float4 acc = make_float4(0.f, 0.f, 0.f, 0.f);
    #pragma unroll
    for (int g = 0; g < 8; g++) {
        float x0 = __shfl_sync(0xffffffffu, xq.x, g, 8);
        float x1 = __shfl_sync(0xffffffffu, xq.y, g, 8);
        float x2 = __shfl_sync(0xffffffffu, xq.z, g, 8);
        float x3 = __shfl_sync(0xffffffffu, xq.w, g, 8);
        float4 w0 = sw[(4 * g + 0) * 8 + sub];
        float4 w1 = sw[(4 * g + 1) * 8 + sub];
        float4 w2 = sw[(4 * g + 2) * 8 + sub];
        float4 w3 = sw[(4 * g + 3) * 8 + sub];
        acc.x += x0 * w0.x + x1 * w1.x + x2 * w2.x + x3 * w3.x;
        acc.y += x0 * w0.y + x1 * w1.y + x2 * w2.y + x3 * w3.y;
        acc.z += x0 * w0.z + x1 * w1.z + x2 * w2.z + x3 * w3.z;
        acc.w += x0 * w0.w + x1 * w1.w + x2 * w2.w + x3 * w3.w;
    }
    int idx = node * 8 + sub;
    Y[idx] = acc;
    float di = dinv[node];
    float s = di * di;
    float4 b = ((const float4*)bias)[sub];
    OUT[idx] = make_float4(acc.x * s + b.x, acc.y * s + b.y,
                           acc.z * s + b.z, acc.w * s + b.w);
}

// fc1 fused into GCN1's gemm: h = relu(x@fc1_w + fc1_b); y = h@w1; out = y*dinv^2+b1
__global__ void gemm_fc1(const float4* __restrict__ x,
                         const float* __restrict__ fc1w, const float* __restrict__ fc1b,
                         const float* __restrict__ w, const float* __restrict__ b,
                         const float* __restrict__ dinv,
                         float4* __restrict__ Y, float4* __restrict__ OUT, int n)
{
    __shared__ float4 sw[256];
    __shared__ float4 sfw[32];   // fc1_w [4,32] as 4x8 float4
    __shared__ float4 sfb[8];
    int tid = threadIdx.x;
    sw[tid] = ((const float4*)w)[tid];
    if (tid < 32) sfw[tid] = ((const float4*)fc1w)[tid];
    if (tid < 8)  sfb[tid] = ((const float4*)fc1b)[tid];
    __syncthreads();
    int node = blockIdx.x * 32 + (tid >> 3);
    int sub = tid & 7;
    if (node >= n) return;           // n % 32 == 0: never divergent
    float4 xr = x[node];             // x[node, 0..3]
    float4 h = sfb[sub];
    float4 r0 = sfw[0 * 8 + sub], r1 = sfw[1 * 8 + sub];
    float4 r2 = sfw[2 * 8 + sub], r3 = sfw[3 * 8 + sub];
    h.x += xr.x * r0.x + xr.y * r1.x + xr.z * r2.x + xr.w * r3.x;
    h.y += xr.x * r0.y + xr.y * r1.y + xr.z * r2.y + xr.w * r3.y;
    h.z += xr.x * r0.z + xr.y * r1.z + xr.z * r2.z + xr.w * r3.z;
    h.w += xr.x * r0.w + xr.y * r1.w + xr.z * r2.w + xr.w * r3.w;
    h = relu4(h);
    gemm_core(h, sw, node, sub, b, dinv, Y, OUT);
}

// Downsample fused: xq = relu(in[(2ix)*win + 2iy])
__global__ void gemm_down(const float4* __restrict__ in,
                          const float* __restrict__ w, const float* __restrict__ b,
                          const float* __restrict__ dinv,
                          float4* __restrict__ Y, float4* __restrict__ OUT,
                          int n, int hy, int win)
{
    __shared__ float4 sw[256];
    int tid = threadIdx.x;
    sw[tid] = ((const float4*)w)[tid];
    __syncthreads();
    int node = blockIdx.x * 32 + (tid >> 3);
    int sub = tid & 7;
    if (node >= n) return;
    int ix = node / hy, iy = node - ix * hy;
    int sn = (2 * ix) * win + 2 * iy;
    float4 xq = relu4(in[sn * 8 + sub]);
    gemm_core(xq, sw, node, sub, b, dinv, Y, OUT);
}

// Upsample+residual fused: xq = relu(base[node]) + relu(coarse[(ix/2)*(hy/2)+iy/2])
__global__ void gemm_upadd(const float4* __restrict__ base,
                           const float4* __restrict__ coarse,
                           const float* __restrict__ w, const float* __restrict__ b,
                           const float* __restrict__ dinv,
                           float4* __restrict__ Y, float4* __restrict__ OUT,
                           int n, int hy)
{
    __shared__ float4 sw[256];
    int tid = threadIdx.x;
    sw[tid] = ((const float4*)w)[tid];
    __syncthreads();
    int node = blockIdx.x * 32 + (tid >> 3);
    int sub = tid & 7;
    if (node >= n) return;
    int ix = node / hy, iy = node - ix * hy;
    int cn = (ix >> 1) * (hy >> 1) + (iy >> 1);
    float4 xb = relu4(base[node * 8 + sub]);
    float4 xc = relu4(coarse[cn * 8 + sub]);
    float4 xq = make_float4(xb.x + xc.x, xb.y + xc.y, xb.z + xc.z, xb.w + xc.w);
    gemm_core(xq, sw, node, sub, b, dinv, Y, OUT);
}

// ---------------- edge scatter: 8 threads/edge, red.v4.f32 ----------------
__global__ void scatter_vec(const float4* __restrict__ Y,
                            const float* __restrict__ dinv,
                            const int* __restrict__ src, const int* __restrict__ dst,
                            float4* __restrict__ OUT, int ne)
{
    int t = blockIdx.x * blockDim.x + threadIdx.x;
    int e = t >> 3, sub = t & 7;
    if (e >= ne) return;
    int s = __ldg(&src[e]);
    int d = __ldg(&dst[e]);
    float norm = __ldg(&dinv[s]) * __ldg(&dinv[d]);
    float4 v = Y[s * 8 + sub];
    v.x *= norm; v.y *= norm; v.z *= norm; v.w *= norm;
    float4* p = OUT + d * 8 + sub;
    asm volatile("red.global.add.v4.f32 [%0], {%1, %2, %3, %4};"
                 :: "l"(p), "f"(v.x), "f"(v.y), "f"(v.z), "f"(v.w) : "memory");
}

// ---------------- fc2: relu(h)[n,32] @ [32,3] + b ----------------
__global__ void fc2_vec(const float4* __restrict__ H,
                        const float* __restrict__ w, const float* __restrict__ b,
                        float* __restrict__ out, int n)
{
    __shared__ float sw[96];
    int tid = threadIdx.x;
    if (tid < 96) sw[tid] = w[tid];
    __syncthreads();
    int node = blockIdx.x * 32 + (tid >> 3);
    int sub = tid & 7;
    if (node >= n) return;
    float4 v = relu4(H[node * 8 + sub]);
    float p0 = 0.f, p1 = 0.f, p2 = 0.f;
    int c = 4 * sub;
    p0 = v.x * sw[(c+0)*3+0] + v.y * sw[(c+1)*3+0] + v.z * sw[(c+2)*3+0] + v.w * sw[(c+3)*3+0];
    p1 = v.x * sw[(c+0)*3+1] + v.y * sw[(c+1)*3+1] + v.z * sw[(c+2)*3+1] + v.w * sw[(c+3)*3+1];
    p2 = v.x * sw[(c+0)*3+2] + v.y * sw[(c+1)*3+2] + v.z * sw[(c+2)*3+2] + v.w * sw[(c+3)*3+2];
    #pragma unroll
    for (int off = 4; off; off >>= 1) {
        p0 += __shfl_down_sync(0xffffffffu, p0, off, 8);
        p1 += __shfl_down_sync(0xffffffffu, p1, off, 8);
        p2 += __shfl_down_sync(0xffffffffu, p2, off, 8);
    }
    if (sub == 0) {
        out[node * 3 + 0] = p0 + __ldg(&b[0]);
        out[node * 3 + 1] = p1 + __ldg(&b[1]);
        out[node * 3 + 2] = p2 + __ldg(&b[2]);
    }
}

// ---------------------------------------------------------------------------
static inline int ceil_div(int a, int b) { return (a + b - 1) / b; }

extern "C" void kernel_launch(void* const* d_in, const int* in_sizes, int n_in,
                              void* d_out, int out_size) {
    const float* x     = (const float*)d_in[0];
    const float* fc1_w = (const float*)d_in[1];
    const float* fc1_b = (const float*)d_in[2];
    const float* w1 = (const float*)d_in[3];  const float* b1 = (const float*)d_in[4];
    const float* w2 = (const float*)d_in[5];  const float* b2 = (const float*)d_in[6];
    const float* w3 = (const float*)d_in[7];  const float* b3 = (const float*)d_in[8];
    const float* w4 = (const float*)d_in[9];  const float* b4 = (const float*)d_in[10];
    const float* w5 = (const float*)d_in[11]; const float* b5 = (const float*)d_in[12];
    const float* fc2_w = (const float*)d_in[13];
    const float* fc2_b = (const float*)d_in[14];
    const int* ei0 = (const int*)d_in[18];
    const int* ei1 = (const int*)d_in[19];
    const int* ei2 = (const int*)d_in[20];
    float* out = (float*)d_out;

    float4 *Y, *H, *G5, *G2, *G4, *G3;
    float *dv0, *dv1, *dv2;
    cudaGetSymbolAddress((void**)&Y,  g_Y);
    cudaGetSymbolAddress((void**)&H,  g_H);
    cudaGetSymbolAddress((void**)&G5, g_G5);
    cudaGetSymbolAddress((void**)&G2, g_G2);
    cudaGetSymbolAddress((void**)&G4, g_G4);
    cudaGetSymbolAddress((void**)&G3, g_G3);
    cudaGetSymbolAddress((void**)&dv0, g_dv0);
    cudaGetSymbolAddress((void**)&dv1, g_dv1);
    cudaGetSymbolAddress((void**)&dv2, g_dv2);

    const int TB = 256;

    // 0-3: degrees -> dinv
    deg_init_all<<<ceil_div(N0 + N1 + N2, TB), TB>>>(dv0, dv1, dv2);
    deg_acc<<<ceil_div(E0, TB), TB>>>(ei0 + E0, dv0, E0);
    deg_acc2<<<ceil_div(E1 + E2, TB), TB>>>(ei1 + E1, dv1, ei2 + E2, dv2);
    deg_rsqrt_all<<<ceil_div(N0 + N1 + N2, TB), TB>>>(dv0, dv1, dv2);

    // 4: GCN1 gemm (fc1 fused) -> Y, H(init)
    gemm_fc1<<<N0 / 32, TB>>>((const float4*)x, fc1_w, fc1_b, w1, b1, dv0, Y, H, N0);
    // 5: GCN1 scatter  (<- ncu -s 5 captures this launch)
    scatter_vec<<<ceil_div(E0 * 8, TB), TB>>>(Y, dv0, ei0, ei0 + E0, H, E0);

    // 6-7: GCN2 (level 1), input = relu(H) downsampled
    gemm_down<<<N1 / 32, TB>>>(H, w2, b2, dv1, Y, G2, N1, NYg / 2, NYg);
    scatter_vec<<<ceil_div(E1 * 8, TB), TB>>>(Y, dv1, ei1, ei1 + E1, G2, E1);

    // 8-9: GCN3 (level 2), input = relu(G2) downsampled
    gemm_down<<<N2 / 32, TB>>>(G2, w3, b3, dv2, Y, G3, N2, NYg / 4, NYg / 2);
    scatter_vec<<<ceil_div(E2 * 8, TB), TB>>>(Y, dv2, ei2, ei2 + E2, G3, E2);

    // 10-11: GCN4 (level 1), input = relu(G2) + up2(relu(G3))
    gemm_upadd<<<N1 / 32, TB>>>(G2, G3, w4, b4, dv1, Y, G4, N1, NYg / 2);
    scatter_vec<<<ceil_div(E1 * 8, TB), TB>>>(Y, dv1, ei1, ei1 + E1, G4, E1);

    // 12-13: GCN5 (level 0), input = relu(H) + up2(relu(G4))
    gemm_upadd<<<N0 / 32, TB>>>(H, G4, w5, b5, dv0, Y, G5, N0, NYg);
    scatter_vec<<<ceil_div(E0 * 8, TB), TB>>>(Y, dv0, ei0, ei0 + E0, G5, E0);

    // 14: fc2
    fc2_vec<<<N0 / 32, TB>>>(G5, fc2_w, fc2_b, out, N0);

    (void)in_sizes; (void)n_in; (void)out_size;
}

// round 3
// speedup vs baseline: 3.7290x; 1.4387x over previous
#include <cuda_runtime.h>

// Net_multi_11390253269716: 3-level GCN U-Net, 784x480 grid, C=32.
// R3: CSR gather (no float atomics), f32x2 gemm with 4-node weight reuse,
//     fc2 fused into final gather.

#define NXg 784
#define NYg 480
#define C 32
#define N0 (NXg * NYg)        // 376320
#define N1 (N0 / 4)           // 94080
#define N2 (N0 / 16)          // 23520
#define E0 (4 * N0)           // 1505280
#define E1 (4 * N1)           // 376320
#define E2 (4 * N2)           // 94080
#define ETOT (E0 + E1 + E2)   // 1975680
#define M (N0 + N1 + N2)      // 493920 (concat node count)
#define GB1 N0                // global base of level-1 nodes
#define GB2 (N0 + N1)
#define SCAN_NBLK ((M + 1023) / 1024)   // 483

typedef unsigned long long ull;

// ---------------- scratch ----------------
__device__ float4 g_Y [N0 * 8];   // x@w temp (levels reuse prefix)
__device__ float4 g_H [N0 * 8];   // GCN1 out
__device__ float4 g_G2[N1 * 8];
__device__ float4 g_G4[N1 * 8];
__device__ float4 g_G3[N2 * 8];
__device__ int   g_cnt[M];        // histogram, then cursors
__device__ int   g_rowptr[M + 1];
__device__ int   g_eix[ETOT];     // src node id, grouped by dst
__device__ float g_dinv[M];
__device__ int   g_bsum[SCAN_NBLK];

// ---------------- f32x2 helpers ----------------
__device__ __forceinline__ ull pk2(float a, float b) {
    ull r; asm("mov.b64 %0, {%1, %2};" : "=l"(r) : "f"(a), "f"(b)); return r;
}
__device__ __forceinline__ ull fma2_(ull a, ull b, ull c) {
    ull d; asm("fma.rn.f32x2 %0, %1, %2, %3;" : "=l"(d) : "l"(a), "l"(b), "l"(c)); return d;
}
__device__ __forceinline__ float2 up2_(ull v) {
    float2 f; asm("mov.b64 {%0, %1}, %2;" : "=f"(f.x), "=f"(f.y) : "l"(v)); return f;
}
__device__ __forceinline__ float4 relu4(float4 v) {
    v.x = fmaxf(v.x, 0.f); v.y = fmaxf(v.y, 0.f);
    v.z = fmaxf(v.z, 0.f); v.w = fmaxf(v.w, 0.f);
    return v;
}

// ---------------- CSR build ----------------
__global__ void zero_cnt() {
    int i = blockIdx.x * blockDim.x + threadIdx.x;
    if (i < M) g_cnt[i] = 0;
}

__global__ void hist3(const int* __restrict__ d0, const int* __restrict__ d1,
                      const int* __restrict__ d2) {
    int t = blockIdx.x * blockDim.x + threadIdx.x;
    int g;
    if (t < E0) g = d0[t];
    else if (t < E0 + E1) g = GB1 + d1[t - E0];
    else if (t < ETOT) g = GB2 + d2[t - E0 - E1];
    else return;
    atomicAdd(&g_cnt[g], 1);
}

__global__ void scanA() {   // per-1024-block sums
    __shared__ int sb[256];
    int tid = threadIdx.x;
    int base = blockIdx.x * 1024 + tid * 4;
    int v = 0;
    #pragma unroll
    for (int k = 0; k < 4; k++) if (base + k < M) v += g_cnt[base + k];
    sb[tid] = v; __syncthreads();
    for (int off = 128; off; off >>= 1) {
        if (tid < off) sb[tid] += sb[tid + off];
        __syncthreads();
    }
    if (tid == 0) g_bsum[blockIdx.x] = sb[0];
}

__global__ void scanB() {   // exclusive scan of block sums (1 block, 512 thr)
    __shared__ int sb[512];
    int tid = threadIdx.x;
    int v = (tid < SCAN_NBLK) ? g_bsum[tid] : 0;
    sb[tid] = v; __syncthreads();
    for (int off = 1; off < 512; off <<= 1) {
        int t = (tid >= off) ? sb[tid - off] : 0;
        __syncthreads();
        sb[tid] += t;
        __syncthreads();
    }
    if (tid < SCAN_NBLK) g_bsum[tid] = sb[tid] - v;   // exclusive
}

__global__ void scanC() {   // rowptr + dinv + zero cnt (cursors)
    __shared__ int sb[256];
    int tid = threadIdx.x;
    int base = blockIdx.x * 1024 + tid * 4;
    int v[4], p[4], tsum = 0;
    #pragma unroll
    for (int k = 0; k < 4; k++) {
        v[k] = (base + k < M) ? g_cnt[base + k] : 0;
        p[k] = tsum; tsum += v[k];
    }
    sb[tid] = tsum; __syncthreads();
    for (int off = 1; off < 256; off <<= 1) {
        int t = (tid >= off) ? sb[tid - off] : 0;
        __syncthreads();
        sb[tid] += t;
        __syncthreads();
    }
    int off0 = g_bsum[blockIdx.x] + sb[tid] - tsum;
    #pragma unroll
    for (int k = 0; k < 4; k++) {
        int i = base + k;
        if (i < M) {
            g_rowptr[i] = off0 + p[k];
            g_dinv[i] = rsqrtf((float)v[k] + 1.0f);
            g_cnt[i] = 0;
        }
    }
    if (blockIdx.x == 0 && tid == 0) g_rowptr[M] = ETOT;
}

__global__ void fill3(const int* __restrict__ ei0, const int* __restrict__ ei1,
                      const int* __restrict__ ei2) {
    int t = blockIdx.x * blockDim.x + threadIdx.x;
    int g, s;
    if (t < E0)             { g = ei0[E0 + t];            s = ei0[t]; }
    else if (t < E0 + E1)   { int e = t - E0;      g = GB1 + ei1[E1 + e]; s = ei1[e]; }
    else if (t < ETOT)      { int e = t - E0 - E1; g = GB2 + ei2[E2 + e]; s = ei2[e]; }
    else return;
    int pos = g_rowptr[g] + atomicAdd(&g_cnt[g], 1);
    g_eix[pos] = s;
}

// ---------------- gemm: 8 thr/node, 4 nodes/group, f32x2 ----------------
// Computes Y[node] = xq_row @ w (32x32) for 4 nodes per 8-thread group.
#define GEMM_PROLOG(n_)                                                   \
    __shared__ ulonglong2 swu[256];                                       \
    int tid = threadIdx.x;                                                \
    swu[tid] = ((const ulonglong2*)w)[tid];                               \
    int sub = tid & 7;                                                    \
    int nb = (blockIdx.x * 32 + (tid >> 3)) * 4;                          \
    float4 xq[4];

#define GEMM_BODY(n_)                                                     \
    __syncthreads();                                                      \
    ull a01[4] = {0, 0, 0, 0}, a23[4] = {0, 0, 0, 0};                     \
    _Pragma("unroll")                                                     \
    for (int g = 0; g < 8; g++) {                                         \
        ulonglong2 w0 = swu[(4 * g + 0) * 8 + sub];                       \
        ulonglong2 w1 = swu[(4 * g + 1) * 8 + sub];                       \
        ulonglong2 w2 = swu[(4 * g + 2) * 8 + sub];                       \
        ulonglong2 w3 = swu[(4 * g + 3) * 8 + sub];                       \
        _Pragma("unroll")                                                 \
        for (int j = 0; j < 4; j++) {                                     \
            float x0 = __shfl_sync(0xffffffffu, xq[j].x, g, 8);           \
            float x1 = __shfl_sync(0xffffffffu, xq[j].y, g, 8);           \
            float x2 = __shfl_sync(0xffffffffu, xq[j].z, g, 8);           \
            float x3 = __shfl_sync(0xffffffffu, xq[j].w, g, 8);           \
            a01[j] = fma2_(pk2(x0, x0), w0.x, a01[j]);                    \
            a23[j] = fma2_(pk2(x0, x0), w0.y, a23[j]);                    \
            a01[j] = fma2_(pk2(x1, x1), w1.x, a01[j]);                    \
            a23[j] = fma2_(pk2(x1, x1), w1.y, a23[j]);                    \
            a01[j] = fma2_(pk2(x2, x2), w2.x, a01[j]);                    \
            a23[j] = fma2_(pk2(x2, x2), w2.y, a23[j]);                    \
            a01[j] = fma2_(pk2(x3, x3), w3.x, a01[j]);                    \
            a23[j] = fma2_(pk2(x3, x3), w3.y, a23[j]);                    \
        }                                                                 \
    }                                                                     \
    _Pragma("unroll")                                                     \
    for (int j = 0; j < 4; j++)                                           \
        if (nb + j < n_) {                                                \
            ulonglong2 r; r.x = a01[j]; r.y = a23[j];                     \
            ((ulonglong2*)Y)[(nb + j) * 8 + sub] = r;                     \
        }

// fc1 fused: xq = relu(x @ fc1_w + fc1_b)
__global__ void gemm_fc1(const float4* __restrict__ x,
                         const float* __restrict__ fc1w, const float* __restrict__ fc1b,
                         const float* __restrict__ w,
                         float4* __restrict__ Y, int n)
{
    GEMM_PROLOG(n)
    __shared__ float4 sfw[32];
    __shared__ float4 sfb[8];
    if (tid < 32) sfw[tid] = ((const float4*)fc1w)[tid];
    if (tid < 8)  sfb[tid] = ((const float4*)fc1b)[tid];
    __syncthreads();
    float4 r0 = sfw[0 * 8 + sub], r1 = sfw[1 * 8 + sub];
    float4 r2 = sfw[2 * 8 + sub], r3 = sfw[3 * 8 + sub];
    float4 bb = sfb[sub];
    #pragma unroll
    for (int j = 0; j < 4; j++) {
        float4 xr = (nb + j < n) ? x[nb + j] : make_float4(0.f, 0.f, 0.f, 0.f);
        float4 h = bb;
        h.x += xr.x * r0.x + xr.y * r1.x + xr.z * r2.x + xr.w * r3.x;
        h.y += xr.x * r0.y + xr.y * r1.y + xr.z * r2.y + xr.w * r3.y;
        h.z += xr.x * r0.z + xr.y * r1.z + xr.z * r2.z + xr.w * r3.z;
        h.w += xr.x * r0.w + xr.y * r1.w + xr.z * r2.w + xr.w * r3.w;
        xq[j] = relu4(h);
    }
    GEMM_BODY(n)
}

// downsample fused: xq = relu(in[(2ix)*win + 2iy])
__global__ void gemm_down(const float4* __restrict__ in,
                          const float* __restrict__ w,
                          float4* __restrict__ Y, int n, int hy, int win)
{
    GEMM_PROLOG(n)
    #pragma unroll
    for (int j = 0; j < 4; j++) {
        int node = nb + j;
        if (node < n) {
            int ix = node / hy, iy = node - ix * hy;
            int sn = (2 * ix) * win + 2 * iy;
            xq[j] = relu4(in[sn * 8 + sub]);
        } else xq[j] = make_float4(0.f, 0.f, 0.f, 0.f);
    }
    GEMM_BODY(n)
}

// upsample+residual fused
__global__ void gemm_upadd(const float4* __restrict__ base,
                           const float4* __restrict__ coarse,
                           const float* __restrict__ w,
                           float4* __restrict__ Y, int n, int hy)
{
    GEMM_PROLOG(n)
    #pragma unroll
    for (int j = 0; j < 4; j++) {
        int node = nb + j;
        if (node < n) {
            int ix = node / hy, iy = node - ix * hy;
            int cn = (ix >> 1) * (hy >> 1) + (iy >> 1);
            float4 xb = relu4(base[node * 8 + sub]);
            float4 xc = relu4(coarse[cn * 8 + sub]);
            xq[j] = make_float4(xb.x + xc.x, xb.y + xc.y, xb.z + xc.z, xb.w + xc.w);
        } else xq[j] = make_float4(0.f, 0.f, 0.f, 0.f);
    }
    GEMM_BODY(n)
}

// ---------------- gather: OUT[d] = b + Y[d]*dinv^2 + sum Y[s]*dinv_s*dinv_d ----
__device__ __forceinline__ void gather_acc(
    const ulonglong2* __restrict__ Y, int node, int sub, int gbase,
    const float* __restrict__ bias, ull& a01, ull& a23)
{
    float di = g_dinv[gbase + node];
    int beg = g_rowptr[gbase + node];
    int end = g_rowptr[gbase + node + 1];
    float4 bb = ((const float4*)bias)[sub];
    float s2 = di * di;
    ulonglong2 y = Y[node * 8 + sub];
    ull s22 = pk2(s2, s2);
    a01 = fma2_(y.x, s22, pk2(bb.x, bb.y));
    a23 = fma2_(y.y, s22, pk2(bb.z, bb.w));
    for (int p = beg; p < end; p++) {
        int s = g_eix[p];
        float nm = g_dinv[gbase + s] * di;
        ulonglong2 v = Y[s * 8 + sub];
        ull nn = pk2(nm, nm);
        a01 = fma2_(v.x, nn, a01);
        a23 = fma2_(v.y, nn, a23);
    }
}

__global__ void gather(const float4* __restrict__ Yf,
                       const float* __restrict__ bias,
                       float4* __restrict__ OUT, int n, int gbase)
{
    int t = blockIdx.x * blockDim.x + threadIdx.x;
    int node = t >> 3, sub = t & 7;
    if (node >= n) return;
    ull a01, a23;
    gather_acc((const ulonglong2*)Yf, node, sub, gbase, bias, a01, a23);
    ulonglong2 r; r.x = a01; r.y = a23;
    ((ulonglong2*)OUT)[node * 8 + sub] = r;
}

// final gather with fc2 epilogue: out[node,3] = relu(gcn5) @ fc2_w + fc2_b
__global__ void gather_fc2(const float4* __restrict__ Yf,
                           const float* __restrict__ bias,
                           const float* __restrict__ w2, const float* __restrict__ b2,
                           float* __restrict__ out, int n)
{
    __shared__ float sw[96];
    int tid = threadIdx.x;
    if (tid < 96) sw[tid] = w2[tid];
    __syncthreads();
    int t = blockIdx.x * blockDim.x + tid;
    int node = t >> 3, sub = t & 7;
    if (node >= n) return;
    ull a01, a23;
    gather_acc((const ulonglong2*)Yf, node, sub, 0, bias, a01, a23);
    float2 v01 = up2_(a01), v23 = up2_(a23);
    float4 v = relu4(make_float4(v01.x, v01.y, v23.x, v23.y));
    int c = 4 * sub;
    float p0 = v.x * sw[(c+0)*3+0] + v.y * sw[(c+1)*3+0] + v.z * sw[(c+2)*3+0] + v.w * sw[(c+3)*3+0];
    float p1 = v.x * sw[(c+0)*3+1] + v.y * sw[(c+1)*3+1] + v.z * sw[(c+2)*3+1] + v.w * sw[(c+3)*3+1];
    float p2 = v.x * sw[(c+0)*3+2] + v.y * sw[(c+1)*3+2] + v.z * sw[(c+2)*3+2] + v.w * sw[(c+3)*3+2];
    #pragma unroll
    for (int off = 4; off; off >>= 1) {
        p0 += __shfl_down_sync(0xffffffffu, p0, off, 8);
        p1 += __shfl_down_sync(0xffffffffu, p1, off, 8);
        p2 += __shfl_down_sync(0xffffffffu, p2, off, 8);
    }
    if (sub == 0) {
        out[node * 3 + 0] = p0 + __ldg(&b2[0]);
        out[node * 3 + 1] = p1 + __ldg(&b2[1]);
        out[node * 3 + 2] = p2 + __ldg(&b2[2]);
    }
}

// ---------------------------------------------------------------------------
static inline int ceil_div(int a, int b) { return (a + b - 1) / b; }

extern "C" void kernel_launch(void* const* d_in, const int* in_sizes, int n_in,
                              void* d_out, int out_size) {
    const float* x     = (const float*)d_in[0];
    const float* fc1_w = (const float*)d_in[1];
    const float* fc1_b = (const float*)d_in[2];
    const float* w1 = (const float*)d_in[3];  const float* b1 = (const float*)d_in[4];
    const float* w2 = (const float*)d_in[5];  const float* b2 = (const float*)d_in[6];
    const float* w3 = (const float*)d_in[7];  const float* b3 = (const float*)d_in[8];
    const float* w4 = (const float*)d_in[9];  const float* b4 = (const float*)d_in[10];
    const float* w5 = (const float*)d_in[11]; const float* b5 = (const float*)d_in[12];
    const float* fc2_w = (const float*)d_in[13];
    const float* fc2_b = (const float*)d_in[14];
    const int* ei0 = (const int*)d_in[18];
    const int* ei1 = (const int*)d_in[19];
    const int* ei2 = (const int*)d_in[20];
    float* out = (float*)d_out;

    float4 *Y, *H, *G2, *G4, *G3;
    cudaGetSymbolAddress((void**)&Y,  g_Y);
    cudaGetSymbolAddress((void**)&H,  g_H);
    cudaGetSymbolAddress((void**)&G2, g_G2);
    cudaGetSymbolAddress((void**)&G4, g_G4);
    cudaGetSymbolAddress((void**)&G3, g_G3);

    const int TB = 256;

    // CSR build (also produces dinv for all levels)
    zero_cnt<<<ceil_div(M, TB), TB>>>();
    hist3<<<ceil_div(ETOT, TB), TB>>>(ei0 + E0, ei1 + E1, ei2 + E2);
    scanA<<<SCAN_NBLK, 256>>>();
    scanB<<<1, 512>>>();
    scanC<<<SCAN_NBLK, 256>>>();
    fill3<<<ceil_div(ETOT, TB), TB>>>(ei0, ei1, ei2);

    // GCN1 (level 0), fc1 fused
    gemm_fc1<<<ceil_div(N0, 128), TB>>>((const float4*)x, fc1_w, fc1_b, w1, Y, N0);
    gather<<<N0 / 32, TB>>>(Y, b1, H, N0, 0);

    // GCN2 (level 1)
    gemm_down<<<ceil_div(N1, 128), TB>>>(H, w2, Y, N1, NYg / 2, NYg);
    gather<<<N1 / 32, TB>>>(Y, b2, G2, N1, GB1);

    // GCN3 (level 2)
    gemm_down<<<ceil_div(N2, 128), TB>>>(G2, w3, Y, N2, NYg / 4, NYg / 2);
    gather<<<N2 / 32, TB>>>(Y, b3, G3, N2, GB2);

    // GCN4 (level 1)
    gemm_upadd<<<ceil_div(N1, 128), TB>>>(G2, G3, w4, Y, N1, NYg / 2);
    gather<<<N1 / 32, TB>>>(Y, b4, G4, N1, GB1);

    // GCN5 (level 0) + fc2 fused into gather
    gemm_upadd<<<ceil_div(N0, 128), TB>>>(H, G4, w5, Y, N0, NYg);
    gather_fc2<<<N0 / 32, TB>>>(Y, b5, fc2_w, fc2_b, out, N0);

    (void)in_sizes; (void)n_in; (void)out_size;
}